// round 16
// baseline (speedup 1.0000x reference)
#include <cuda_runtime.h>
#include <cuda_bf16.h>

// loss = sum_{b,c,s,h,w} (out[b,c,2s,h,w] - target[b,c,2s+1,h,w])^2 / (C*H*Wd * W/2)
// B=8, C=32, W=16 (s=0..7), H=128, Wd=128.
//
// 2048 slabs (g = flattened b,c,s). Slab g:
//   out float4 base : out4 + (g<<13)          (4096 float4 = 64 KB)
//   tgt float4 base : tgt4 + (g<<13) + 4096   (4096 float4 = 64 KB)
//
// Mainloop: BATCHED loads — 4 out-float4 + 4 tgt-float4 (32 data regs) issued
// before any FMA, 4 batches per slab -> per-thread MLP ~8 outstanding LDG.128
// (vs ~2-3 at regs=32). Occupancy drops to ~44%; R12 measured 33% occ still
// sustains ~79% DRAM, so latency-hiding via per-thread MLP wins.
//
// Completion (R15, measured cheapest): d_out IS the accumulator.
//   - CTA0/thread0 first cancels the previous replay's value via read+red(-old).
//   - Each CTA fire-and-forgets ONE red.add.relaxed.gpu.f32 of its partial,
//     pre-scaled by the exact power-of-two 2^-22, then retires immediately.

#define NBLOCKS 2048
#define NTHREADS 256
#define BATCHES 4         // per slab
#define BATCH_LOADS 4     // float4 pairs per batch

__global__ __launch_bounds__(NTHREADS) void cont_loss_kernel(
    const float4* __restrict__ out4, const float4* __restrict__ tgt4,
    float* __restrict__ result)
{
    // Self-canceling reset of the accumulator (previous replay's value).
    if (blockIdx.x == 0 && threadIdx.x == 0) {
        float old;
        asm volatile("ld.relaxed.gpu.f32 %0, [%1];"
                     : "=f"(old) : "l"(result) : "memory");
        asm volatile("red.add.relaxed.gpu.f32 [%0], %1;"
                     :: "l"(result), "f"(-old) : "memory");
    }

    const long long base = ((long long)blockIdx.x << 13);
    const float4* __restrict__ op = out4 + base + threadIdx.x;
    const float4* __restrict__ tp = tgt4 + base + 4096 + threadIdx.x;

    float a0 = 0.0f, a1 = 0.0f, a2 = 0.0f, a3 = 0.0f;
    #pragma unroll
    for (int k = 0; k < BATCHES; k++) {
        float4 o[BATCH_LOADS], t[BATCH_LOADS];
        // issue all 8 loads back-to-back (front-batched -> high MLP)
        #pragma unroll
        for (int j = 0; j < BATCH_LOADS; j++)
            o[j] = op[(k * BATCH_LOADS + j) * NTHREADS];
        #pragma unroll
        for (int j = 0; j < BATCH_LOADS; j++)
            t[j] = tp[(k * BATCH_LOADS + j) * NTHREADS];
        // then consume
        #pragma unroll
        for (int j = 0; j < BATCH_LOADS; j++) {
            float d0 = o[j].x - t[j].x;
            float d1 = o[j].y - t[j].y;
            float d2 = o[j].z - t[j].z;
            float d3 = o[j].w - t[j].w;
            a0 = fmaf(d0, d0, a0);
            a1 = fmaf(d1, d1, a1);
            a2 = fmaf(d2, d2, a2);
            a3 = fmaf(d3, d3, a3);
        }
    }
    float acc = (a0 + a1) + (a2 + a3);

    // deterministic in-block smem tree
    __shared__ float sbuf[NTHREADS];
    sbuf[threadIdx.x] = acc;
    __syncthreads();
    #pragma unroll
    for (int ofs = NTHREADS / 2; ofs > 0; ofs >>= 1) {
        if (threadIdx.x < ofs) sbuf[threadIdx.x] += sbuf[threadIdx.x + ofs];
        __syncthreads();
    }

    if (threadIdx.x == 0) {
        // 2^-22: exact scaling (exponent shift only)
        float scaled = sbuf[0] * 2.384185791015625e-07f;
        asm volatile("red.add.relaxed.gpu.f32 [%0], %1;"
                     :: "l"(result), "f"(scaled) : "memory");
    }
}

extern "C" void kernel_launch(void* const* d_in, const int* in_sizes, int n_in,
                              void* d_out, int out_size)
{
    const float4* out4 = (const float4*)d_in[0];
    const float4* tgt4 = (const float4*)d_in[1];
    float* o = (float*)d_out;

    cont_loss_kernel<<<NBLOCKS, NTHREADS>>>(out4, tgt4, o);
}